// round 4
// baseline (speedup 1.0000x reference)
#include <cuda_runtime.h>
#include <cstddef>

// ---------------------------------------------------------------------------
// GRU recurrence, persistent-kernel fp32 baseline.
//
// Shapes: x (B=512, T=512, IN=128), W_ih (768,128), W_hh (768,256),
//         bias_g (768), bias_n (256), w_lin (128,256), bias_out (128)
// Output: h_final @ w_lin^T + bias_out  -> (512, 128) fp32
//
// Design:
//   * ONE persistent kernel, 128 blocks (<=148 SMs -> all co-resident),
//     grid-wide generation barrier once per timestep.
//   * Per block: batch tile of 64 rows x 16 hidden units (= 48 gate columns
//     r/z/n). Its 48x384 weight slice ([W_ih | W_hh], gate-permuted) lives in
//     padded SMEM for the whole run.
//   * Per step: stage x_t tile (64x128) + h tile (64x256) into padded SMEM,
//     fp32 FFMA GEMM with register tile 4 rows x {r,z,n}, fused GRU epilogue,
//     write h_new into the ping-pong global h buffer, grid barrier.
//   * n-gate x-part and h-part are accumulated separately (reference applies
//     r only to the h-part + bias_n).
//   * h is double buffered: step t reads g_h[t&1], writes g_h[(t+1)&1], so a
//     single barrier per step is sufficient (no RAW/WAR hazard).
//   * All g_h reads use __ldcg (L2) — L1 is not coherent across blocks and
//     the same addresses are re-read every other step.
// ---------------------------------------------------------------------------

#define BB      512
#define TT      512
#define IN_DIM  128
#define HH      256
#define OUT_DIM 128

#define NBLK 128     // 8 batch chunks x 16 hidden chunks
#define NTHR 256
#define MB   64      // batch rows per block
#define UHN  16      // hidden units per block
#define NC   48      // gate columns per block (r,z,n for 16 units)

// padded SMEM strides (floats): %32 != 0 for conflict-free LDS.128,
// *4 bytes % 16 == 0 for alignment
#define AXS 132      // x tile row stride   (64 x 132)
#define AHS 260      // h tile row stride   (64 x 260)
#define WTS 388      // W slice row stride  (48 x 388)

#define SMEM_FLOATS (MB*AXS + MB*AHS + NC*WTS)
#define SMEM_BYTES  (SMEM_FLOATS * 4)

__device__ unsigned g_count = 0;   // barrier arrival counter (returns to 0)
__device__ unsigned g_gen   = 0;   // barrier generation (monotonic, wrap-safe)
__device__ float    g_h[2][BB][HH];   // ping-pong hidden state (1 MB)

__device__ __forceinline__ float sigmoid_f(float v) {
    return 1.0f / (1.0f + __expf(-v));
}

extern "C" __global__ void __launch_bounds__(NTHR, 1)
gru_persistent_kernel(const float* __restrict__ x,
                      const float* __restrict__ wih,
                      const float* __restrict__ whh,
                      const float* __restrict__ bg,
                      const float* __restrict__ bn,
                      const float* __restrict__ wlin,
                      const float* __restrict__ bout,
                      float* __restrict__ out)
{
    extern __shared__ float sm[];
    float* Ax = sm;                  // [MB][AXS]  x_t tile
    float* Ah = Ax + MB * AXS;       // [MB][AHS]  h tile
    float* Wt = Ah + MB * AHS;       // [NC][WTS]  weight slice (persists)

    const int tid = threadIdx.x;
    const int bid = blockIdx.x;
    const int bc  = bid >> 4;        // batch chunk 0..7
    const int gch = bid & 15;        // hidden chunk 0..15
    const int b0  = bc * MB;
    const int u0  = gch * UHN;

    const int tx = tid & 15;         // hidden unit within chunk
    const int ty = tid >> 4;         // row group (4 rows each)
    const int u  = u0 + tx;          // global hidden unit of this thread

    // Snapshot barrier generation before any block can possibly advance it.
    const unsigned base = *(volatile unsigned*)&g_gen;

    // Per-thread biases (constant across rows and steps).
    const float bgr = bg[u];
    const float bgz = bg[HH + u];
    const float bgn = bg[2 * HH + u];
    const float bnn = bn[u];

    // ---- Stage weight slice once: rows = [r(16); z(16); n(16)] of this
    //      hidden chunk, cols = [W_ih(128) | W_hh(256)] ----
    for (int i = tid; i < NC * 96; i += NTHR) {
        const int c = i / 96, q = i % 96;      // q indexes float4s along K
        const int gt  = c >> 4;                // 0=r, 1=z, 2=n
        const int row = gt * HH + u0 + (c & 15);
        float4 v;
        if (q < 32) v = __ldg((const float4*)(wih + (size_t)row * IN_DIM) + q);
        else        v = __ldg((const float4*)(whh + (size_t)row * HH) + (q - 32));
        *(float4*)(Wt + c * WTS + 4 * q) = v;
    }

    const float* wr = Wt + tx * WTS;
    const float* wz = Wt + (16 + tx) * WTS;
    const float* wn = Wt + (32 + tx) * WTS;

    // ================= time loop =================
    for (int t = 0; t < TT; ++t) {
        const int cur = t & 1;
        const int nxt = cur ^ 1;

        // ---- stage x_t tile (64 x 128) ----
        for (int i = tid; i < MB * 32; i += NTHR) {
            const int m = i >> 5, q = i & 31;
            float4 v = __ldg((const float4*)(x + ((size_t)(b0 + m) * TT + t) * IN_DIM) + q);
            *(float4*)(Ax + m * AXS + 4 * q) = v;
        }
        // ---- stage h tile (64 x 256); zeros at t==0 ----
        for (int i = tid; i < MB * 64; i += NTHR) {
            const int m = i >> 6, q = i & 63;
            float4 v;
            if (t > 0) v = __ldcg((const float4*)(&g_h[cur][b0 + m][0]) + q);
            else       { v.x = 0.f; v.y = 0.f; v.z = 0.f; v.w = 0.f; }
            *(float4*)(Ah + m * AHS + 4 * q) = v;
        }
        __syncthreads();

        float ar[4]  = {0.f, 0.f, 0.f, 0.f};
        float az[4]  = {0.f, 0.f, 0.f, 0.f};
        float anx[4] = {0.f, 0.f, 0.f, 0.f};   // n-gate, x part
        float anh[4] = {0.f, 0.f, 0.f, 0.f};   // n-gate, h part

        const float* a0  = Ax + (4 * ty) * AXS;
        const float* ah0 = Ah + (4 * ty) * AHS;

        // ---- K loop, x part (k = 0..127) ----
        #pragma unroll 2
        for (int k = 0; k < IN_DIM; k += 4) {
            const float4 br = *(const float4*)(wr + k);
            const float4 bz = *(const float4*)(wz + k);
            const float4 bv = *(const float4*)(wn + k);
            #pragma unroll
            for (int r = 0; r < 4; ++r) {
                const float4 a = *(const float4*)(a0 + r * AXS + k);
                ar[r]  = fmaf(a.x, br.x, ar[r]);  ar[r]  = fmaf(a.y, br.y, ar[r]);
                ar[r]  = fmaf(a.z, br.z, ar[r]);  ar[r]  = fmaf(a.w, br.w, ar[r]);
                az[r]  = fmaf(a.x, bz.x, az[r]);  az[r]  = fmaf(a.y, bz.y, az[r]);
                az[r]  = fmaf(a.z, bz.z, az[r]);  az[r]  = fmaf(a.w, bz.w, az[r]);
                anx[r] = fmaf(a.x, bv.x, anx[r]); anx[r] = fmaf(a.y, bv.y, anx[r]);
                anx[r] = fmaf(a.z, bv.z, anx[r]); anx[r] = fmaf(a.w, bv.w, anx[r]);
            }
        }
        // ---- K loop, h part (k = 0..255, weight offset +128) ----
        #pragma unroll 2
        for (int k = 0; k < HH; k += 4) {
            const float4 br = *(const float4*)(wr + IN_DIM + k);
            const float4 bz = *(const float4*)(wz + IN_DIM + k);
            const float4 bv = *(const float4*)(wn + IN_DIM + k);
            #pragma unroll
            for (int r = 0; r < 4; ++r) {
                const float4 a = *(const float4*)(ah0 + r * AHS + k);
                ar[r]  = fmaf(a.x, br.x, ar[r]);  ar[r]  = fmaf(a.y, br.y, ar[r]);
                ar[r]  = fmaf(a.z, br.z, ar[r]);  ar[r]  = fmaf(a.w, br.w, ar[r]);
                az[r]  = fmaf(a.x, bz.x, az[r]);  az[r]  = fmaf(a.y, bz.y, az[r]);
                az[r]  = fmaf(a.z, bz.z, az[r]);  az[r]  = fmaf(a.w, bz.w, az[r]);
                anh[r] = fmaf(a.x, bv.x, anh[r]); anh[r] = fmaf(a.y, bv.y, anh[r]);
                anh[r] = fmaf(a.z, bv.z, anh[r]); anh[r] = fmaf(a.w, bv.w, anh[r]);
            }
        }

        // ---- fused GRU epilogue ----
        #pragma unroll
        for (int r = 0; r < 4; ++r) {
            const int m = 4 * ty + r;
            const float rr   = sigmoid_f(ar[r] + bgr);
            const float zz   = sigmoid_f(az[r] + bgz);
            const float nn   = tanhf(anx[r] + bgn + rr * (anh[r] + bnn));
            const float hold = Ah[m * AHS + u];              // h_{t-1}[m][u]
            g_h[nxt][b0 + m][u] = nn + zz * (hold - nn);
        }

        // ---- grid-wide barrier (one per step) ----
        __syncthreads();                 // everyone done with SMEM + stores issued
        if (tid == 0) {
            __threadfence();             // publish h_new before arrival
            const unsigned old = atomicAdd(&g_count, 1);
            if (old == NBLK - 1) {
                atomicExch(&g_count, 0);
                __threadfence();
                atomicAdd(&g_gen, 1);
            } else {
                while (*(volatile unsigned*)&g_gen - base < (unsigned)(t + 1)) { }
            }
            __threadfence();             // acquire side
        }
        __syncthreads();
    }

    // ============ final projection: out = h_final @ w_lin^T + bias_out ============
    // h_final lives in g_h[0] (T is even). Block computes rows [b0,b0+64),
    // output cols [gch*8, gch*8+8).
    for (int i = tid; i < MB * 64; i += NTHR) {
        const int m = i >> 6, q = i & 63;
        float4 v = __ldcg((const float4*)(&g_h[0][b0 + m][0]) + q);
        *(float4*)(Ah + m * AHS + 4 * q) = v;
    }
    const int c0 = gch * 8;
    for (int i = tid; i < 8 * 64; i += NTHR) {
        const int c = i >> 6, q = i & 63;
        float4 v = __ldg((const float4*)(wlin + (size_t)(c0 + c) * HH) + q);
        *(float4*)(Wt + c * WTS + 4 * q) = v;
    }
    __syncthreads();

    #pragma unroll
    for (int p = 0; p < 2; ++p) {
        const int o = tid + p * NTHR;        // 0..511
        const int m = o >> 3;
        const int c = o & 7;
        const float* hv = Ah + m * AHS;
        const float* wv = Wt + c * WTS;
        float acc = 0.f;
        #pragma unroll 8
        for (int k = 0; k < HH; ++k) acc = fmaf(hv[k], wv[k], acc);
        out[(size_t)(b0 + m) * OUT_DIM + c0 + c] = acc + bout[c0 + c];
    }
}

// ---------------------------------------------------------------------------
extern "C" void kernel_launch(void* const* d_in, const int* in_sizes, int n_in,
                              void* d_out, int out_size)
{
    (void)in_sizes; (void)n_in; (void)out_size;
    const float* x    = (const float*)d_in[0];
    const float* wih  = (const float*)d_in[1];
    const float* whh  = (const float*)d_in[2];
    const float* bg   = (const float*)d_in[3];
    const float* bn   = (const float*)d_in[4];
    const float* wlin = (const float*)d_in[5];
    const float* bout = (const float*)d_in[6];
    float* out = (float*)d_out;

    // Idempotent, capture-safe (not a stream operation).
    cudaFuncSetAttribute(gru_persistent_kernel,
                         cudaFuncAttributeMaxDynamicSharedMemorySize, SMEM_BYTES);

    gru_persistent_kernel<<<NBLK, NTHR, SMEM_BYTES>>>(
        x, wih, whh, bg, bn, wlin, bout, out);
}

// round 6
// speedup vs baseline: 1.8280x; 1.8280x over previous
#include <cuda_runtime.h>
#include <cuda_bf16.h>
#include <mma.h>
#include <cstdint>
#include <cstddef>

using namespace nvcuda;

// ===========================================================================
// GRU recurrence on HMMA (wmma bf16, 3-term split: hi*hi + lo*hi + hi*lo).
// Target is plain sm_100 (harness compiles compute_100 — no tcgen05 allowed).
//
// Phase A (pregemm, 2048 blocks): IG[t][b][768] = x @ W_ih^T -> fp32 scratch.
// Phase B (persistent, 128 blocks): per step HG = h @ W_hh^T via wmma,
//   fused GRU epilogue, h as bf16 hi/lo ping-pong, grid barrier per step,
//   final projection fused at the end.
// ===========================================================================

#define BB      512
#define TT      512
#define IN_DIM  128
#define HH      256
#define G3      768
#define OUT_DIM 128

#define NBLK 128         // Phase B: 16 mchunks(32 rows) x 8 nchunks(32 units)
#define NTHR 256

__device__ float          g_ig[(size_t)TT * BB * G3];   // 805 MB scratch
__device__ __nv_bfloat16  g_hh[2][BB][HH];              // h hi, ping-pong
__device__ __nv_bfloat16  g_hl[2][BB][HH];              // h lo
__device__ unsigned       g_count = 0;
__device__ unsigned       g_gen   = 0;

// ---------------- helpers ----------------
__device__ __forceinline__ uint32_t pack2(unsigned short a, unsigned short b) {
    return (uint32_t)a | ((uint32_t)b << 16);
}
__device__ __forceinline__ void split8(float4 f0, float4 f1, uint4& hv, uint4& lv) {
    float f[8] = {f0.x, f0.y, f0.z, f0.w, f1.x, f1.y, f1.z, f1.w};
    unsigned short hs[8], ls[8];
#pragma unroll
    for (int j = 0; j < 8; ++j) {
        __nv_bfloat16 h = __float2bfloat16(f[j]);
        __nv_bfloat16 l = __float2bfloat16(f[j] - __bfloat162float(h));
        hs[j] = __bfloat16_as_ushort(h);
        ls[j] = __bfloat16_as_ushort(l);
    }
    hv.x = pack2(hs[0], hs[1]); hv.y = pack2(hs[2], hs[3]);
    hv.z = pack2(hs[4], hs[5]); hv.w = pack2(hs[6], hs[7]);
    lv.x = pack2(ls[0], ls[1]); lv.y = pack2(ls[2], ls[3]);
    lv.z = pack2(ls[4], ls[5]); lv.w = pack2(ls[6], ls[7]);
}
__device__ __forceinline__ void unpack8(uint4 v, float* f) {
    uint32_t w[4] = {v.x, v.y, v.z, v.w};
#pragma unroll
    for (int j = 0; j < 4; ++j) {
        __nv_bfloat162 h = *reinterpret_cast<__nv_bfloat162*>(&w[j]);
        f[2 * j]     = __bfloat162float(h.x);
        f[2 * j + 1] = __bfloat162float(h.y);
    }
}
__device__ __forceinline__ float sigmoid_f(float v) {
    return 1.0f / (1.0f + __expf(-v));
}

typedef wmma::fragment<wmma::matrix_a, 16, 16, 16, __nv_bfloat16, wmma::row_major> FragA;
typedef wmma::fragment<wmma::matrix_b, 16, 16, 16, __nv_bfloat16, wmma::col_major> FragB;
typedef wmma::fragment<wmma::accumulator, 16, 16, 16, float> FragC;

// ===========================================================================
// Phase A: IG = x @ W_ih^T.  2048 blocks x 128 rows (row r = b*512 + t, one b
// per block). Inner loop over 6 N-tiles of 128 gate cols. K=128, 3 passes.
// SMEM (bf16, ld=136): XH | XL | BH | BL.
// ===========================================================================
#define LDA   136
#define XH_OFF 0
#define XL_OFF 34816
#define BH_OFF 69632
#define BL_OFF 104448
#define PRE_SMEM 139264

extern "C" __global__ void __launch_bounds__(NTHR, 1)
pregemm_kernel(const float* __restrict__ x, const float* __restrict__ wih)
{
    extern __shared__ char sm[];
    __nv_bfloat16* XH = (__nv_bfloat16*)(sm + XH_OFF);
    __nv_bfloat16* XL = (__nv_bfloat16*)(sm + XL_OFF);
    __nv_bfloat16* BH = (__nv_bfloat16*)(sm + BH_OFF);
    __nv_bfloat16* BL = (__nv_bfloat16*)(sm + BL_OFF);

    const int tid = threadIdx.x, wid = tid >> 5;
    const size_t r0 = (size_t)blockIdx.x * 128;
    const int b   = (int)(r0 >> 9);       // batch index (constant per block)
    const int t0b = (int)(r0 & 511);      // first timestep of this block

    // stage X rows [r0, r0+128) x 128 cols, fp32 -> bf16 hi/lo (once)
    for (int i = tid; i < 128 * 16; i += NTHR) {
        const int row = i >> 4, q = i & 15;
        const float* src = x + (r0 + row) * IN_DIM + q * 8;
        float4 f0 = __ldg((const float4*)src);
        float4 f1 = __ldg((const float4*)(src + 4));
        uint4 hv, lv; split8(f0, f1, hv, lv);
        *(uint4*)(XH + row * LDA + q * 8) = hv;
        *(uint4*)(XL + row * LDA + q * 8) = lv;
    }

    const int m0 = wid * 16;              // warp's m-tile

    for (int nt = 0; nt < 6; ++nt) {
        __syncthreads();                  // X ready / previous tile's reads done
        const int n0 = nt * 128;
        // stage B = W_ih rows [n0, n0+128) x 128
        for (int i = tid; i < 128 * 16; i += NTHR) {
            const int row = i >> 4, q = i & 15;
            const float* src = wih + (size_t)(n0 + row) * IN_DIM + q * 8;
            float4 f0 = __ldg((const float4*)src);
            float4 f1 = __ldg((const float4*)(src + 4));
            uint4 hv, lv; split8(f0, f1, hv, lv);
            *(uint4*)(BH + row * LDA + q * 8) = hv;
            *(uint4*)(BL + row * LDA + q * 8) = lv;
        }
        __syncthreads();

        FragC acc[8];
#pragma unroll
        for (int j = 0; j < 8; ++j) wmma::fill_fragment(acc[j], 0.0f);

#pragma unroll
        for (int p = 0; p < 3; ++p) {
            const __nv_bfloat16* Ab = (p == 1) ? XL : XH;
            const __nv_bfloat16* Bb = (p == 2) ? BL : BH;
#pragma unroll
            for (int k = 0; k < 8; ++k) {
                FragA af;
                wmma::load_matrix_sync(af, Ab + m0 * LDA + k * 16, LDA);
#pragma unroll
                for (int j = 0; j < 8; ++j) {
                    FragB bf;
                    wmma::load_matrix_sync(bf, Bb + (j * 16) * LDA + k * 16, LDA);
                    wmma::mma_sync(acc[j], af, bf, acc[j]);
                }
            }
        }
        // store: tile rows are consecutive t (b fixed) -> ldm = BB*G3
        float* dst = g_ig + (size_t)(t0b + m0) * ((size_t)BB * G3)
                   + (size_t)b * G3 + n0;
#pragma unroll
        for (int j = 0; j < 8; ++j)
            wmma::store_matrix_sync(dst + j * 16, acc[j],
                                    (unsigned)(BB * G3), wmma::mem_row_major);
    }
}

// ===========================================================================
// Phase B: persistent recurrence. 128 blocks = 16 mchunks x 8 nchunks.
// Block tile: 32 batch rows x 32 hidden units (96 gate cols r/z/n).
// 8 warps: (m-tile 0/1) x (n-group 0/1 of 48 cols) x (k-half 0/1),
// k-half partials reduced through two SMEM gate buffers.
// SMEM: bias(128f) | AH | AL (32x264 bf16) | WH | WL (96x264 bf16) | GA | GB.
// ===========================================================================
#define LDH   264
#define LDGT  100
#define LB_AH 512
#define LB_AL 17408
#define LB_WH 34304
#define LB_WL 84992
#define LB_GA 135680
#define LB_GB 148480
#define LOOP_SMEM 161280

extern "C" __global__ void __launch_bounds__(NTHR, 1)
gru_loop_kernel(const float* __restrict__ whh,
                const float* __restrict__ bg,
                const float* __restrict__ bn,
                const float* __restrict__ wlin,
                const float* __restrict__ bout,
                float* __restrict__ out)
{
    extern __shared__ char sm[];
    float* sb = (float*)sm;                       // 128 bias floats
    __nv_bfloat16* AH = (__nv_bfloat16*)(sm + LB_AH);
    __nv_bfloat16* AL = (__nv_bfloat16*)(sm + LB_AL);
    __nv_bfloat16* WH = (__nv_bfloat16*)(sm + LB_WH);
    __nv_bfloat16* WL = (__nv_bfloat16*)(sm + LB_WL);
    float* GA = (float*)(sm + LB_GA);             // k-half 0 partial gates
    float* GB = (float*)(sm + LB_GB);             // k-half 1 partial gates

    const int tid = threadIdx.x, wid = tid >> 5;
    const int mchunk = blockIdx.x >> 3, nchunk = blockIdx.x & 7;
    const int b0 = mchunk * 32, u0 = nchunk * 32;
    const unsigned gbase = *(volatile unsigned*)&g_gen;

    if (tid < 32) {
        sb[tid]      = bg[u0 + tid];
        sb[32 + tid] = bg[HH + u0 + tid];
        sb[64 + tid] = bg[2 * HH + u0 + tid];
        sb[96 + tid] = bn[u0 + tid];
    }
    // W_hh slice: 96 gate rows [r(32); z(32); n(32)] x K=256, split, once.
    for (int i = tid; i < 96 * 32; i += NTHR) {
        const int c = i >> 5, q = i & 31;
        const int row = (c >> 5) * HH + u0 + (c & 31);
        const float* src = whh + (size_t)row * HH + q * 8;
        float4 f0 = __ldg((const float4*)src);
        float4 f1 = __ldg((const float4*)(src + 4));
        uint4 hv, lv; split8(f0, f1, hv, lv);
        *(uint4*)(WH + c * LDH + q * 8) = hv;
        *(uint4*)(WL + c * LDH + q * 8) = lv;
    }
    // zero the h tile (t==0 uses it directly)
    {
        const uint4 z = make_uint4(0, 0, 0, 0);
        for (int i = tid; i < 32 * 32; i += NTHR) {
            const int row = i >> 5, q = i & 31;
            *(uint4*)(AH + row * LDH + q * 8) = z;
            *(uint4*)(AL + row * LDH + q * 8) = z;
        }
    }
    __syncthreads();

    const int m0    = (wid & 1) * 16;
    const int ngrp  = (wid >> 1) & 1;
    const int khalf = wid >> 2;
    const int kbase = khalf * 128;
    float* gout = khalf ? GB : GA;

    const int row_e = tid >> 3, part = tid & 7;    // epilogue: row x 4 units
    const int b_e = b0 + row_e;

    // ===================== time loop =====================
    for (int t = 0; t < TT; ++t) {
        const int cur = t & 1, nxt = cur ^ 1;

        // prefetch IG for the epilogue (hides DRAM behind staging+MMA)
        const float* igp = g_ig + ((size_t)t * BB + b_e) * G3 + u0 + part * 4;
        const float4 ig_r = __ldg((const float4*)igp);
        const float4 ig_z = __ldg((const float4*)(igp + HH));
        const float4 ig_n = __ldg((const float4*)(igp + 2 * HH));

        // stage h tile 32 x 256 hi/lo (skip at t==0, SMEM pre-zeroed)
        if (t > 0) {
            for (int i = tid; i < 32 * 32; i += NTHR) {
                const int row = i >> 5, q = i & 31;
                uint4 vh = __ldcg((const uint4*)&g_hh[cur][b0 + row][q * 8]);
                uint4 vl = __ldcg((const uint4*)&g_hl[cur][b0 + row][q * 8]);
                *(uint4*)(AH + row * LDH + q * 8) = vh;
                *(uint4*)(AL + row * LDH + q * 8) = vl;
            }
        }
        __syncthreads();

        // ---- wmma: acc[j] over this warp's (m0, ngrp, khalf) ----
        FragC acc[3];
#pragma unroll
        for (int j = 0; j < 3; ++j) wmma::fill_fragment(acc[j], 0.0f);
#pragma unroll
        for (int p = 0; p < 3; ++p) {
            const __nv_bfloat16* Ab = (p == 1) ? AL : AH;
            const __nv_bfloat16* Wb = (p == 2) ? WL : WH;
#pragma unroll
            for (int kk = 0; kk < 8; ++kk) {
                const int k = kbase + kk * 16;
                FragA af;
                wmma::load_matrix_sync(af, Ab + m0 * LDH + k, LDH);
#pragma unroll
                for (int j = 0; j < 3; ++j) {
                    FragB bf;
                    wmma::load_matrix_sync(
                        bf, Wb + (ngrp * 48 + j * 16) * LDH + k, LDH);
                    wmma::mma_sync(acc[j], af, bf, acc[j]);
                }
            }
        }
#pragma unroll
        for (int j = 0; j < 3; ++j)
            wmma::store_matrix_sync(gout + m0 * LDGT + ngrp * 48 + j * 16,
                                    acc[j], LDGT, wmma::mem_row_major);
        __syncthreads();

        // ---- fused GRU epilogue: thread -> (row_e, units part*4..+4) ----
        {
            const float igr[4] = {ig_r.x, ig_r.y, ig_r.z, ig_r.w};
            const float igz[4] = {ig_z.x, ig_z.y, ig_z.z, ig_z.w};
            const float ign[4] = {ig_n.x, ig_n.y, ig_n.z, ig_n.w};
            unsigned short hs[4], ls[4];
#pragma unroll
            for (int j = 0; j < 4; ++j) {
                const int ul = part * 4 + j;
                const float hgr = GA[row_e * LDGT + ul]      + GB[row_e * LDGT + ul];
                const float hgz = GA[row_e * LDGT + 32 + ul] + GB[row_e * LDGT + 32 + ul];
                const float hgn = GA[row_e * LDGT + 64 + ul] + GB[row_e * LDGT + 64 + ul];
                const float hof = __bfloat162float(AH[row_e * LDH + u0 + ul])
                                + __bfloat162float(AL[row_e * LDH + u0 + ul]);
                const float rr = sigmoid_f(igr[j] + sb[ul] + hgr);
                const float zz = sigmoid_f(igz[j] + sb[32 + ul] + hgz);
                const float nn = tanhf(ign[j] + sb[64 + ul] + rr * (hgn + sb[96 + ul]));
                const float h  = nn + zz * (hof - nn);
                const __nv_bfloat16 hb = __float2bfloat16(h);
                const __nv_bfloat16 lb = __float2bfloat16(h - __bfloat162float(hb));
                hs[j] = __bfloat16_as_ushort(hb);
                ls[j] = __bfloat16_as_ushort(lb);
            }
            *(uint2*)&g_hh[nxt][b_e][u0 + part * 4] =
                make_uint2(pack2(hs[0], hs[1]), pack2(hs[2], hs[3]));
            *(uint2*)&g_hl[nxt][b_e][u0 + part * 4] =
                make_uint2(pack2(ls[0], ls[1]), pack2(ls[2], ls[3]));
        }

        // ---- grid-wide barrier (proven gen-counter pattern) ----
        __syncthreads();
        if (tid == 0) {
            __threadfence();
            const unsigned old = atomicAdd(&g_count, 1);
            if (old == NBLK - 1) {
                atomicExch(&g_count, 0);
                __threadfence();
                atomicAdd(&g_gen, 1);
            } else {
                while (*(volatile unsigned*)&g_gen - gbase < (unsigned)(t + 1)) { }
            }
            __threadfence();
        }
        __syncthreads();
    }

    // ====== final projection: out = h_final @ w_lin^T + bias_out ======
    // h_final in buffer 0 (T even). Rows [b0,b0+32), cols [nchunk*16, +16).
    {
        float* HP = (float*)sm;            // [32][260]
        float* WP = HP + 32 * 260;         // [16][260]
        for (int i = tid; i < 32 * 32; i += NTHR) {
            const int row = i >> 5, q = i & 31;
            uint4 vh = __ldcg((const uint4*)&g_hh[0][b0 + row][q * 8]);
            uint4 vl = __ldcg((const uint4*)&g_hl[0][b0 + row][q * 8]);
            float fh[8], fl[8]; unpack8(vh, fh); unpack8(vl, fl);
            float* d = HP + row * 260 + q * 8;
#pragma unroll
            for (int j = 0; j < 8; ++j) d[j] = fh[j] + fl[j];
        }
        const int c0 = nchunk * 16;
        for (int i = tid; i < 16 * 32; i += NTHR) {
            const int c = i >> 5, q = i & 31;
            const float* src = wlin + (size_t)(c0 + c) * HH + q * 8;
            float4 f0 = __ldg((const float4*)src);
            float4 f1 = __ldg((const float4*)(src + 4));
            float* d = WP + c * 260 + q * 8;
            *(float4*)d       = f0;
            *(float4*)(d + 4) = f1;
        }
        __syncthreads();
#pragma unroll
        for (int p = 0; p < 2; ++p) {
            const int o = tid + p * NTHR;          // 0..511
            const int m = o >> 4, c = o & 15;
            const float* hv = HP + m * 260;
            const float* wv = WP + c * 260;
            float acc = 0.f;
#pragma unroll 8
            for (int k = 0; k < HH; ++k) acc = fmaf(hv[k], wv[k], acc);
            out[(size_t)(b0 + m) * OUT_DIM + c0 + c] = acc + bout[c0 + c];
        }
    }
}

// ---------------------------------------------------------------------------
extern "C" void kernel_launch(void* const* d_in, const int* in_sizes, int n_in,
                              void* d_out, int out_size)
{
    (void)in_sizes; (void)n_in; (void)out_size;
    const float* x    = (const float*)d_in[0];
    const float* wih  = (const float*)d_in[1];
    const float* whh  = (const float*)d_in[2];
    const float* bg   = (const float*)d_in[3];
    const float* bn   = (const float*)d_in[4];
    const float* wlin = (const float*)d_in[5];
    const float* bout = (const float*)d_in[6];
    float* out = (float*)d_out;

    cudaFuncSetAttribute(pregemm_kernel,
                         cudaFuncAttributeMaxDynamicSharedMemorySize, PRE_SMEM);
    cudaFuncSetAttribute(gru_loop_kernel,
                         cudaFuncAttributeMaxDynamicSharedMemorySize, LOOP_SMEM);

    pregemm_kernel<<<2048, NTHR, PRE_SMEM>>>(x, wih);
    gru_loop_kernel<<<NBLK, NTHR, LOOP_SMEM>>>(whh, bg, bn, wlin, bout, out);
}